// round 7
// baseline (speedup 1.0000x reference)
#include <cuda_runtime.h>
#include <cuda_fp16.h>
#include <math.h>
#include <stdint.h>

// ---------------------------------------------------------------------------
// PointSwinBlock on GB300 (sm_103): fp16 mma.sync.m16n8k16 GEMMs (fp32 accum),
// BM128xBN256 tiles, 512 threads, ldmatrix fragments, 3-stage cp.async.
// B=2, N=65536, DIM=256, HEADS=8, HEAD_DIM=32, WS=64, MLP=1024
// ---------------------------------------------------------------------------

#define DIMC   256
#define NTOK   131072
#define NPB    65536
#define HEADS  8
#define HDIM   32
#define WS     64
#define MLPD   1024

// scratch (allocation-free: __device__ globals), GEMM operands in half
__device__ __half g_ln  [(size_t)NTOK * DIMC];
__device__ __half g_qkv [(size_t)NTOK * 768];
__device__ __half g_attn[(size_t)NTOK * DIMC];
__device__ __half g_h   [(size_t)NTOK * MLPD];
// transposed weights [N,K] in half
__device__ __half g_wqkvT[768 * DIMC];
__device__ __half g_woutT[DIMC * DIMC];
__device__ __half g_w1T  [MLPD * DIMC];
__device__ __half g_w2T  [DIMC * MLPD];

__device__ __forceinline__ uint32_t smem_u32(const void* p) {
    uint32_t a;
    asm("{ .reg .u64 t; cvta.to.shared.u64 t, %1; cvt.u32.u64 %0, t; }"
        : "=r"(a) : "l"(p));
    return a;
}

__device__ __forceinline__ void cpa16(uint32_t dst, const void* src) {
    asm volatile("cp.async.cg.shared.global [%0], [%1], 16;"
                 :: "r"(dst), "l"(src) : "memory");
}
#define CPA_COMMIT() asm volatile("cp.async.commit_group;" ::: "memory")

__device__ __forceinline__ void ldsm4(uint32_t& r0, uint32_t& r1,
                                      uint32_t& r2, uint32_t& r3,
                                      uint32_t addr) {
    asm volatile("ldmatrix.sync.aligned.m8n8.x4.shared.b16 {%0,%1,%2,%3}, [%4];"
                 : "=r"(r0), "=r"(r1), "=r"(r2), "=r"(r3) : "r"(addr));
}

__device__ __forceinline__ void mma_f16(float* d, const uint32_t* a,
                                        const uint32_t* b) {
    asm volatile(
        "mma.sync.aligned.m16n8k16.row.col.f32.f16.f16.f32 "
        "{%0,%1,%2,%3}, {%4,%5,%6,%7}, {%8,%9}, {%0,%1,%2,%3};"
        : "+f"(d[0]), "+f"(d[1]), "+f"(d[2]), "+f"(d[3])
        : "r"(a[0]), "r"(a[1]), "r"(a[2]), "r"(a[3]),
          "r"(b[0]), "r"(b[1]));
}

__device__ __forceinline__ float gelu_exact(float v)
{
    return 0.5f * v * (1.f + erff(v * 0.7071067811865476f));
}

// ---------------------------------------------------------------------------
// LayerNorm: one block per row, 256 threads. fp32 in -> half out.
// ---------------------------------------------------------------------------
__global__ void ln_kernel(const float* __restrict__ x,
                          const float* __restrict__ g,
                          const float* __restrict__ b,
                          __half* __restrict__ y)
{
    long row = blockIdx.x;
    int  t   = threadIdx.x;
    float v  = x[row * DIMC + t];
    float s  = v, s2 = v * v;
    #pragma unroll
    for (int o = 16; o; o >>= 1) {
        s  += __shfl_xor_sync(0xffffffffu, s,  o);
        s2 += __shfl_xor_sync(0xffffffffu, s2, o);
    }
    __shared__ float ss[8], ss2[8];
    int w = t >> 5, l = t & 31;
    if (l == 0) { ss[w] = s; ss2[w] = s2; }
    __syncthreads();
    if (t < 32) {
        float a  = (l < 8) ? ss[l]  : 0.f;
        float a2 = (l < 8) ? ss2[l] : 0.f;
        #pragma unroll
        for (int o = 4; o; o >>= 1) {
            a  += __shfl_xor_sync(0xffffffffu, a,  o);
            a2 += __shfl_xor_sync(0xffffffffu, a2, o);
        }
        if (l == 0) { ss[0] = a; ss2[0] = a2; }
    }
    __syncthreads();
    float mu  = ss[0]  * (1.f / DIMC);
    float var = ss2[0] * (1.f / DIMC) - mu * mu;
    float inv = rsqrtf(var + 1e-5f);
    y[row * DIMC + t] = __float2half((v - mu) * inv * g[t] + b[t]);
}

// ---------------------------------------------------------------------------
// Merged weight transpose: 4 matrices in one launch. fp32 [R,C] -> half [C,R]
// tile counts: wqkv 24x8=192, wout 8x8=64, w1 32x8=256, w2 8x32=256 -> 768
// ---------------------------------------------------------------------------
__global__ void transpose_all_kernel(const float* __restrict__ wqkv,
                                     const float* __restrict__ wout,
                                     const float* __restrict__ w1,
                                     const float* __restrict__ w2,
                                     __half* __restrict__ owqkv,
                                     __half* __restrict__ owout,
                                     __half* __restrict__ ow1,
                                     __half* __restrict__ ow2)
{
    __shared__ float t[32][33];
    int bid = blockIdx.x;
    const float* in; __half* out; int R, C, tx_, ty_;
    if (bid < 192)      { in = wqkv; out = owqkv; R = DIMC; C = 768;
                          tx_ = bid % 24; ty_ = bid / 24; }
    else if (bid < 256) { bid -= 192; in = wout; out = owout; R = DIMC; C = DIMC;
                          tx_ = bid % 8;  ty_ = bid / 8; }
    else if (bid < 512) { bid -= 256; in = w1;   out = ow1;   R = DIMC; C = MLPD;
                          tx_ = bid % 32; ty_ = bid / 32; }
    else                { bid -= 512; in = w2;   out = ow2;   R = MLPD; C = DIMC;
                          tx_ = bid % 8;  ty_ = bid / 8; }
    int bx = tx_ * 32, by = ty_ * 32;
    #pragma unroll
    for (int i = threadIdx.y; i < 32; i += 8)
        t[i][threadIdx.x] = in[(long)(by + i) * C + bx + threadIdx.x];
    __syncthreads();
    #pragma unroll
    for (int i = threadIdx.y; i < 32; i += 8)
        out[(long)(bx + i) * R + by + threadIdx.x] =
            __float2half(t[threadIdx.x][i]);
}

// ---------------------------------------------------------------------------
// fp16 GEMM: C[M,N] = A[M,K] @ Bt[N,K]^T (+ epilogue), fp32 accumulate.
// 128x256 block tile, BK=64 halfs (128B rows, xor swizzle), 16 warps
// (2m x 8n, warp tile 64x32), ldmatrix.x4 fragments, 3-stage cp.async,
// 144KB smem, 1 CTA/SM (16 warps = 4 per SMSP).
// ---------------------------------------------------------------------------
#define EPI_NONE      0     // half out
#define EPI_BIAS_RES  1     // float out: acc + bias + res
#define EPI_GELU_BIAS 2     // half out: gelu(acc + bias)
#define EPI_BIAS_ACC  3     // float out: C += acc + bias

#define BM  128
#define BN  256
#define BKH 64               // halfs per chunk = 128 bytes per row
#define A_BYTES   16384      // 128 rows * 128B
#define B_BYTES   32768      // 256 rows * 128B
#define STG_BYTES (A_BYTES + B_BYTES)          // 49152
#define STAGES    3
#define GEMM_SMEM_BYTES (STAGES * STG_BYTES)   // 147456
#define GTHREADS  512

template <int EPI>
__global__ __launch_bounds__(GTHREADS, 1)
void hgemm(const __half* __restrict__ A, const __half* __restrict__ Bt,
           void* __restrict__ Cv,
           const float* __restrict__ bias,
           const float* __restrict__ res,
           int M, int N, int K)
{
    extern __shared__ char smem[];
    uint32_t sbase = smem_u32(smem);

    int  tid    = threadIdx.x;
    int  lane   = tid & 31;
    int  wid    = tid >> 5;
    int  warp_m = wid >> 3;          // 0..1 (64 rows)
    int  warp_n = wid & 7;           // 0..7 (32 cols)
    long m0     = (long)blockIdx.y * BM;
    int  n0     = blockIdx.x * BN;
    int  nc     = K / BKH;

    int l_row = tid >> 3;            // 0..63
    int l_grp = tid & 7;             // 16B group (8 halfs)
    uint32_t l_off = (uint32_t)(l_row * 128 + ((l_grp ^ (l_row & 7)) << 4));

    auto ldgsts = [&](int kc, int st) {
        uint32_t sb = sbase + (uint32_t)st * STG_BYTES + l_off;
        const __half* Ap = A  + (m0 + l_row) * K + kc * BKH + l_grp * 8;
        #pragma unroll
        for (int it = 0; it < 2; it++)
            cpa16(sb + (uint32_t)(it * 64 * 128), Ap + (long)(it * 64) * K);
        const __half* Bp = Bt + ((long)n0 + l_row) * K + kc * BKH + l_grp * 8;
        #pragma unroll
        for (int it = 0; it < 4; it++)
            cpa16(sb + (uint32_t)(A_BYTES + it * 64 * 128),
                  Bp + (long)(it * 64) * K);
        CPA_COMMIT();
    };

    float acc[4][4][4];
    #pragma unroll
    for (int i = 0; i < 4; i++)
        #pragma unroll
        for (int j = 0; j < 4; j++)
            #pragma unroll
            for (int e = 0; e < 4; e++) acc[i][j][e] = 0.f;

    ldgsts(0, 0);
    if (nc > 1) ldgsts(1, 1);

    // ldmatrix lane addressing precompute
    int a_row_l = (lane & 15);           // m offset within 16
    int a_kg_l  = (lane >> 4);           // 0=klo, 1=khi
    int b_row_l = ((lane >> 4) << 3) + (lane & 7);   // n offset within 16
    int b_kg_l  = (lane >> 3) & 1;       // klo/khi

    for (int c = 0; c < nc; c++) {
        if (c + 2 < nc) ldgsts(c + 2, (c + 2) % STAGES);

        int rem = nc - 1 - c; if (rem > 2) rem = 2;
        if (rem == 2)      asm volatile("cp.async.wait_group 2;" ::: "memory");
        else if (rem == 1) asm volatile("cp.async.wait_group 1;" ::: "memory");
        else               asm volatile("cp.async.wait_group 0;" ::: "memory");
        __syncthreads();

        uint32_t smA = sbase + (uint32_t)(c % STAGES) * STG_BYTES;
        uint32_t smB = smA + A_BYTES;

        #pragma unroll
        for (int ks = 0; ks < 4; ks++) {
            uint32_t af[4][4];
            #pragma unroll
            for (int mf = 0; mf < 4; mf++) {
                int row  = warp_m * 64 + mf * 16 + a_row_l;
                int grpk = ks * 2 + a_kg_l;
                uint32_t addr = smA + row * 128 +
                                (((grpk ^ (row & 7)) & 7) << 4);
                ldsm4(af[mf][0], af[mf][1], af[mf][2], af[mf][3], addr);
            }
            uint32_t bf[4][2];
            #pragma unroll
            for (int np = 0; np < 2; np++) {
                int row  = warp_n * 32 + np * 16 + b_row_l;
                int grpk = ks * 2 + b_kg_l;
                uint32_t addr = smB + row * 128 +
                                (((grpk ^ (row & 7)) & 7) << 4);
                uint32_t r0, r1, r2, r3;
                ldsm4(r0, r1, r2, r3, addr);
                bf[np * 2][0]     = r0; bf[np * 2][1]     = r1;
                bf[np * 2 + 1][0] = r2; bf[np * 2 + 1][1] = r3;
            }
            #pragma unroll
            for (int mf = 0; mf < 4; mf++)
                #pragma unroll
                for (int nf = 0; nf < 4; nf++)
                    mma_f16(acc[mf][nf], af[mf], bf[nf]);
        }
        __syncthreads();
    }

    // epilogue: frag rows g, g+8; cols 2q, 2q+1
    int g = lane >> 2;
    int q = lane & 3;

    float2 bv[4];
    if (EPI != EPI_NONE) {
        #pragma unroll
        for (int nf = 0; nf < 4; nf++) {
            int col = n0 + warp_n * 32 + nf * 8 + q * 2;
            bv[nf] = *reinterpret_cast<const float2*>(&bias[col]);
        }
    }

    #pragma unroll
    for (int mf = 0; mf < 4; mf++) {
        long r0 = m0 + warp_m * 64 + mf * 16 + g;
        long r1 = r0 + 8;
        #pragma unroll
        for (int nf = 0; nf < 4; nf++) {
            int col = n0 + warp_n * 32 + nf * 8 + q * 2;
            float2 v0 = make_float2(acc[mf][nf][0], acc[mf][nf][1]);
            float2 v1 = make_float2(acc[mf][nf][2], acc[mf][nf][3]);
            if (EPI == EPI_NONE) {
                __half* C = (__half*)Cv;
                *reinterpret_cast<__half2*>(&C[r0 * N + col]) =
                    __floats2half2_rn(v0.x, v0.y);
                *reinterpret_cast<__half2*>(&C[r1 * N + col]) =
                    __floats2half2_rn(v1.x, v1.y);
            } else if (EPI == EPI_GELU_BIAS) {
                __half* C = (__half*)Cv;
                *reinterpret_cast<__half2*>(&C[r0 * N + col]) =
                    __floats2half2_rn(gelu_exact(v0.x + bv[nf].x),
                                      gelu_exact(v0.y + bv[nf].y));
                *reinterpret_cast<__half2*>(&C[r1 * N + col]) =
                    __floats2half2_rn(gelu_exact(v1.x + bv[nf].x),
                                      gelu_exact(v1.y + bv[nf].y));
            } else if (EPI == EPI_BIAS_RES) {
                float* C = (float*)Cv;
                float2 e0 = *reinterpret_cast<const float2*>(&res[r0 * N + col]);
                float2 e1 = *reinterpret_cast<const float2*>(&res[r1 * N + col]);
                v0.x += bv[nf].x + e0.x; v0.y += bv[nf].y + e0.y;
                v1.x += bv[nf].x + e1.x; v1.y += bv[nf].y + e1.y;
                *reinterpret_cast<float2*>(&C[r0 * N + col]) = v0;
                *reinterpret_cast<float2*>(&C[r1 * N + col]) = v1;
            } else { // EPI_BIAS_ACC
                float* C = (float*)Cv;
                float2 e0 = *reinterpret_cast<const float2*>(&C[r0 * N + col]);
                float2 e1 = *reinterpret_cast<const float2*>(&C[r1 * N + col]);
                v0.x += bv[nf].x + e0.x; v0.y += bv[nf].y + e0.y;
                v1.x += bv[nf].x + e1.x; v1.y += bv[nf].y + e1.y;
                *reinterpret_cast<float2*>(&C[r0 * N + col]) = v0;
                *reinterpret_cast<float2*>(&C[r1 * N + col]) = v1;
            }
        }
    }
}

// ---------------------------------------------------------------------------
// Shifted-window attention: half qkv in, fp32 math, half out.
// One block per (window, head); batch passed as param (split for ncu aim).
// ---------------------------------------------------------------------------
__global__ __launch_bounds__(256)
void attn_kernel(const __half* __restrict__ qkv,
                 const float* __restrict__ pos,
                 __half* __restrict__ out, int b)
{
    int w   = blockIdx.x;
    int h   = blockIdx.y;
    int tid = threadIdx.x;

    __shared__ float q[WS][HDIM], k[WS][HDIM], v[WS][HDIM];
    __shared__ float dots[WS][WS + 1];

    {
        int row = tid >> 2;
        int grp = tid & 3;
        long t = (long)b * NPB + ((w * WS + WS / 2 + row) & (NPB - 1));
        const __half* base = qkv + t * 768 + h * HDIM + grp * 8;
        #pragma unroll
        for (int sel = 0; sel < 3; sel++) {
            uint4 raw = *reinterpret_cast<const uint4*>(base + sel * 256);
            float* dst = (sel == 0) ? &q[row][grp * 8]
                       : (sel == 1) ? &k[row][grp * 8] : &v[row][grp * 8];
            const __half2* hp = reinterpret_cast<const __half2*>(&raw);
            #pragma unroll
            for (int e = 0; e < 4; e++) {
                float2 f = __half22float2(hp[e]);
                dst[2 * e]     = f.x;
                dst[2 * e + 1] = f.y;
            }
        }
    }
    __syncthreads();

    const float scale = 0.17677669529663687f;
    #pragma unroll
    for (int it = 0; it < 16; it++) {
        int e = tid + it * 256;
        int i = e >> 6, j = e & 63;
        float s = 0.f;
        #pragma unroll
        for (int d = 0; d < HDIM; d++) s = fmaf(q[i][d], k[j][d], s);
        dots[i][j] = s * scale + pos[i * WS + j];
    }
    __syncthreads();

    if (tid < WS) {
        float m = -INFINITY;
        #pragma unroll 8
        for (int j = 0; j < WS; j++) m = fmaxf(m, dots[tid][j]);
        float sum = 0.f;
        #pragma unroll 8
        for (int j = 0; j < WS; j++) {
            float e = expf(dots[tid][j] - m);
            dots[tid][j] = e;
            sum += e;
        }
        float inv = 1.f / sum;
        #pragma unroll 8
        for (int j = 0; j < WS; j++) dots[tid][j] *= inv;
    }
    __syncthreads();

    #pragma unroll
    for (int it = 0; it < 8; it++) {
        int e = tid + it * 256;
        int i = e >> 5, d = e & 31;
        float s = 0.f;
        #pragma unroll
        for (int j = 0; j < WS; j++) s = fmaf(dots[i][j], v[j][d], s);
        long t = (long)b * NPB + ((w * WS + WS / 2 + i) & (NPB - 1));
        out[t * DIMC + h * HDIM + d] = __float2half(s);
    }
}

// ---------------------------------------------------------------------------
// launch
// ---------------------------------------------------------------------------
extern "C" void kernel_launch(void* const* d_in, const int* in_sizes, int n_in,
                              void* d_out, int out_size)
{
    const float* x      = (const float*)d_in[0];
    const float* w_qkv  = (const float*)d_in[1];
    const float* w_out  = (const float*)d_in[2];
    const float* b_out  = (const float*)d_in[3];
    const float* pos    = (const float*)d_in[4];
    const float* ln1_g  = (const float*)d_in[5];
    const float* ln1_b  = (const float*)d_in[6];
    const float* w1     = (const float*)d_in[7];
    const float* b1     = (const float*)d_in[8];
    const float* w2     = (const float*)d_in[9];
    const float* b2     = (const float*)d_in[10];
    const float* ln2_g  = (const float*)d_in[11];
    const float* ln2_b  = (const float*)d_in[12];
    float* out = (float*)d_out;

    int tokens = in_sizes[0] / DIMC;   // 131072

    __half *p_ln, *p_qkv, *p_attn, *p_h, *p_wqkvT, *p_woutT, *p_w1T, *p_w2T;
    cudaGetSymbolAddress((void**)&p_ln,    g_ln);
    cudaGetSymbolAddress((void**)&p_qkv,   g_qkv);
    cudaGetSymbolAddress((void**)&p_attn,  g_attn);
    cudaGetSymbolAddress((void**)&p_h,     g_h);
    cudaGetSymbolAddress((void**)&p_wqkvT, g_wqkvT);
    cudaGetSymbolAddress((void**)&p_woutT, g_woutT);
    cudaGetSymbolAddress((void**)&p_w1T,   g_w1T);
    cudaGetSymbolAddress((void**)&p_w2T,   g_w2T);

    cudaFuncSetAttribute(hgemm<EPI_NONE>,
        cudaFuncAttributeMaxDynamicSharedMemorySize, GEMM_SMEM_BYTES);
    cudaFuncSetAttribute(hgemm<EPI_BIAS_RES>,
        cudaFuncAttributeMaxDynamicSharedMemorySize, GEMM_SMEM_BYTES);
    cudaFuncSetAttribute(hgemm<EPI_GELU_BIAS>,
        cudaFuncAttributeMaxDynamicSharedMemorySize, GEMM_SMEM_BYTES);
    cudaFuncSetAttribute(hgemm<EPI_BIAS_ACC>,
        cudaFuncAttributeMaxDynamicSharedMemorySize, GEMM_SMEM_BYTES);

    // 1: merged transposes
    transpose_all_kernel<<<768, dim3(32, 8)>>>(
        w_qkv, w_out, w1, w2, p_wqkvT, p_woutT, p_w1T, p_w2T);

    // 2: LN1
    ln_kernel<<<tokens, 256>>>(x, ln1_g, ln1_b, p_ln);

    // 3: QKV = LN1(x) @ w_qkv  (half out)
    {
        dim3 grid(768 / BN, tokens / BM);
        hgemm<EPI_NONE><<<grid, GTHREADS, GEMM_SMEM_BYTES>>>(
            p_ln, p_wqkvT, p_qkv, nullptr, nullptr, tokens, 768, DIMC);
    }

    // 4,5: windowed attention, one launch per batch (aims ncu -s 5 at proj)
    {
        dim3 grid(NPB / WS, HEADS);
        attn_kernel<<<grid, 256>>>(p_qkv, pos, p_attn, 0);
        attn_kernel<<<grid, 256>>>(p_qkv, pos, p_attn, 1);
    }

    // 6: x2 = x + attn @ w_out + b_out -> d_out (fp32)
    {
        dim3 grid(DIMC / BN, tokens / BM);
        hgemm<EPI_BIAS_RES><<<grid, GTHREADS, GEMM_SMEM_BYTES>>>(
            p_attn, p_woutT, out, b_out, x, tokens, DIMC, DIMC);
    }

    // 7: LN2
    ln_kernel<<<tokens, 256>>>(out, ln2_g, ln2_b, p_ln);

    // 8: h = gelu(LN2 @ w1 + b1)  (half out)
    {
        dim3 grid(MLPD / BN, tokens / BM);
        hgemm<EPI_GELU_BIAS><<<grid, GTHREADS, GEMM_SMEM_BYTES>>>(
            p_ln, p_w1T, p_h, b1, nullptr, tokens, MLPD, DIMC);
    }

    // 9: out += h @ w2 + b2 (fp32)
    {
        dim3 grid(DIMC / BN, tokens / BM);
        hgemm<EPI_BIAS_ACC><<<grid, GTHREADS, GEMM_SMEM_BYTES>>>(
            p_h, p_w2T, out, b2, nullptr, tokens, DIMC, MLPD);
    }
}